// round 1
// baseline (speedup 1.0000x reference)
#include <cuda_runtime.h>

// SimpleSSM: h_t = A*h_{t-1} + B*x_t ; y_t = C*h_t + D*x_t ; LayerNorm over DM.
// BSZ=8, T=4096, DM=1024, fp32.
//
// 3-kernel chunked linear-scan:
//   K1: per-(b,chunk) local scan from zero state -> chunk aggregate c
//   K2: serial combine over chunks -> exclusive chunk-entry states h_in
//   K3: re-scan chunk from h_in, fused LayerNorm, write output

#define BSZ    8
#define SEQT   4096
#define DM     1024
#define NCHUNK 64
#define CLEN   (SEQT / NCHUNK)   // 64
#define ND4    (DM / 4)          // 256 float4 per row
#define LN_EPS 1e-5f

static_assert(CLEN == 64, "A^L squaring count assumes L=64");

// scratch (allocation-free rule: __device__ globals)
__device__ float g_c  [BSZ * NCHUNK * DM];
__device__ float g_hin[BSZ * NCHUNK * DM];

// ---------------------------------------------------------------------------
// K1: chunk-local scan with h0 = 0. Block = (chunk, batch), 256 threads,
// thread t owns 4 consecutive channels (float4). Each timestep the block
// reads one contiguous 4KB row of x.
// ---------------------------------------------------------------------------
__global__ __launch_bounds__(256)
void ssm_k1_chunk_scan(const float* __restrict__ x,
                       const float* __restrict__ A,
                       const float* __restrict__ Bv)
{
    const int b   = blockIdx.y;
    const int ch  = blockIdx.x;
    const int tid = threadIdx.x;

    const float4* x4 = reinterpret_cast<const float4*>(x)
                       + (size_t)(b * SEQT + ch * CLEN) * ND4 + tid;
    const float4 a  = reinterpret_cast<const float4*>(A)[tid];
    const float4 bb = reinterpret_cast<const float4*>(Bv)[tid];

    float4 h = make_float4(0.f, 0.f, 0.f, 0.f);

    #pragma unroll 8
    for (int t = 0; t < CLEN; t++) {
        float4 xv = x4[t * ND4];
        h.x = fmaf(a.x, h.x, bb.x * xv.x);
        h.y = fmaf(a.y, h.y, bb.y * xv.y);
        h.z = fmaf(a.z, h.z, bb.z * xv.z);
        h.w = fmaf(a.w, h.w, bb.w * xv.w);
    }

    reinterpret_cast<float4*>(g_c)[(size_t)(b * NCHUNK + ch) * ND4 + tid] = h;
}

// ---------------------------------------------------------------------------
// K2: serial combine across chunks (per batch, per channel).
// h_in[k] = state entering chunk k;  h_in[k] = A^L * h_in[k-1] + c[k-1].
// Grid: BSZ blocks x 256 threads. Work is trivial (64 iterations, 4 MiB total).
// ---------------------------------------------------------------------------
__global__ __launch_bounds__(256)
void ssm_k2_combine(const float* __restrict__ A)
{
    const int b   = blockIdx.x;
    const int tid = threadIdx.x;

    float4 a = reinterpret_cast<const float4*>(A)[tid];
    float4 aL = a;
    #pragma unroll
    for (int i = 0; i < 6; i++) {            // a^(2^6) = a^64 = A^CLEN
        aL.x *= aL.x; aL.y *= aL.y; aL.z *= aL.z; aL.w *= aL.w;
    }

    const float4* c4  = reinterpret_cast<const float4*>(g_c)
                        + (size_t)b * NCHUNK * ND4 + tid;
    float4* hin4      = reinterpret_cast<float4*>(g_hin)
                        + (size_t)b * NCHUNK * ND4 + tid;

    float4 h = make_float4(0.f, 0.f, 0.f, 0.f);
    for (int k = 0; k < NCHUNK; k++) {
        hin4[k * ND4] = h;                    // exclusive prefix
        float4 cv = c4[k * ND4];
        h.x = fmaf(aL.x, h.x, cv.x);
        h.y = fmaf(aL.y, h.y, cv.y);
        h.z = fmaf(aL.z, h.z, cv.z);
        h.w = fmaf(aL.w, h.w, cv.w);
    }
}

// ---------------------------------------------------------------------------
// K3: re-scan chunk from h_in, compute y, fused LayerNorm over DM, write out.
// Block = (chunk, batch), 256 threads = one full DM row per timestep.
// Per-row block reduction of (sum, sumsq); double-buffered smem so 2 barriers
// per row are race-free. Next row's x load is issued before the barriers.
// ---------------------------------------------------------------------------
__global__ __launch_bounds__(256)
void ssm_k3_final(const float* __restrict__ x,
                  const float* __restrict__ A,
                  const float* __restrict__ Bv,
                  const float* __restrict__ C,
                  const float* __restrict__ Dv,
                  const float* __restrict__ gamma,
                  const float* __restrict__ beta,
                  float* __restrict__ out)
{
    __shared__ float red[2][20];   // [parity][ 16 warp-partials + 2 broadcast ]

    const int b    = blockIdx.y;
    const int ch   = blockIdx.x;
    const int tid  = threadIdx.x;
    const int w    = tid >> 5;
    const int lane = tid & 31;

    const float4 a  = reinterpret_cast<const float4*>(A)[tid];
    const float4 bb = reinterpret_cast<const float4*>(Bv)[tid];
    const float4 cc = reinterpret_cast<const float4*>(C)[tid];
    const float4 dd = reinterpret_cast<const float4*>(Dv)[tid];
    const float4 gg = reinterpret_cast<const float4*>(gamma)[tid];
    const float4 be = reinterpret_cast<const float4*>(beta)[tid];

    float4 h = reinterpret_cast<const float4*>(g_hin)
               [(size_t)(b * NCHUNK + ch) * ND4 + tid];

    const size_t base = (size_t)(b * SEQT + ch * CLEN) * ND4 + tid;
    const float4* x4 = reinterpret_cast<const float4*>(x)   + base;
    float4*       o4 = reinterpret_cast<float4*>(out)       + base;

    float4 xv = x4[0];

    for (int t = 0; t < CLEN; t++) {
        // prefetch next row before the barrier section
        float4 xn;
        if (t + 1 < CLEN) xn = x4[(t + 1) * ND4];

        // recurrence + output
        h.x = fmaf(a.x, h.x, bb.x * xv.x);
        h.y = fmaf(a.y, h.y, bb.y * xv.y);
        h.z = fmaf(a.z, h.z, bb.z * xv.z);
        h.w = fmaf(a.w, h.w, bb.w * xv.w);

        float4 y;
        y.x = fmaf(cc.x, h.x, dd.x * xv.x);
        y.y = fmaf(cc.y, h.y, dd.y * xv.y);
        y.z = fmaf(cc.z, h.z, dd.z * xv.z);
        y.w = fmaf(cc.w, h.w, dd.w * xv.w);

        // block reduction of sum / sumsq over the DM row
        float s = y.x + y.y + y.z + y.w;
        float q = fmaf(y.x, y.x, fmaf(y.y, y.y, fmaf(y.z, y.z, y.w * y.w)));
        #pragma unroll
        for (int o = 16; o > 0; o >>= 1) {
            s += __shfl_xor_sync(0xffffffffu, s, o);
            q += __shfl_xor_sync(0xffffffffu, q, o);
        }
        float* rb = red[t & 1];
        if (lane == 0) { rb[2 * w] = s; rb[2 * w + 1] = q; }
        __syncthreads();
        if (w == 0) {
            float ss = (lane < 8) ? rb[2 * lane]     : 0.f;
            float qq = (lane < 8) ? rb[2 * lane + 1] : 0.f;
            #pragma unroll
            for (int o = 4; o > 0; o >>= 1) {
                ss += __shfl_xor_sync(0xffffffffu, ss, o);
                qq += __shfl_xor_sync(0xffffffffu, qq, o);
            }
            if (lane == 0) { rb[16] = ss; rb[17] = qq; }
        }
        __syncthreads();

        const float mu  = rb[16] * (1.f / DM);
        const float var = rb[17] * (1.f / DM) - mu * mu;
        const float inv = rsqrtf(var + LN_EPS);

        float4 o;
        o.x = fmaf((y.x - mu) * inv, gg.x, be.x);
        o.y = fmaf((y.y - mu) * inv, gg.y, be.y);
        o.z = fmaf((y.z - mu) * inv, gg.z, be.z);
        o.w = fmaf((y.w - mu) * inv, gg.w, be.w);
        o4[t * ND4] = o;

        xv = xn;
    }
}

// ---------------------------------------------------------------------------
extern "C" void kernel_launch(void* const* d_in, const int* in_sizes, int n_in,
                              void* d_out, int out_size)
{
    const float* x     = (const float*)d_in[0];
    const float* A     = (const float*)d_in[1];
    const float* Bv    = (const float*)d_in[2];
    const float* C     = (const float*)d_in[3];
    const float* Dv    = (const float*)d_in[4];
    const float* gamma = (const float*)d_in[5];
    const float* beta  = (const float*)d_in[6];
    float* out = (float*)d_out;

    dim3 grid(NCHUNK, BSZ);
    ssm_k1_chunk_scan<<<grid, 256>>>(x, A, Bv);
    ssm_k2_combine<<<BSZ, 256>>>(A);
    ssm_k3_final<<<grid, 256>>>(x, A, Bv, C, Dv, gamma, beta, out);
}

// round 3
// speedup vs baseline: 1.1843x; 1.1843x over previous
#include <cuda_runtime.h>

// SimpleSSM fused single-pass: decoupled-lookback chunked scan + fused LayerNorm.
// h_t = A*h_{t-1} + B*x_t ; y_t = C*h_t + D*x_t ; LN over DM.
// BSZ=8, T=4096, DM=1024, fp32.
//
// Launch 1: reset per-chunk flags (graph replay safety).
// Launch 2: fused kernel, block = (chunk, batch):
//   P1: local scan from h=0 -> aggregate c, publish (store + threadfence + flag)
//   P2: poll predecessor flags, fold h_in = A^64*h_in + c_j (aggregates L2-hot)
//   P3: re-scan chunk from h_in (x re-read mostly L2 hits), fused LN, write out
//       (output uses streaming stores to avoid evicting x from L2)

#define BSZ    8
#define SEQT   4096
#define DM     1024
#define NCHUNK 64
#define CLEN   (SEQT / NCHUNK)   // 64
#define ND4    (DM / 4)          // 256 float4 per row
#define LN_EPS 1e-5f

static_assert(CLEN == 64, "A^L squaring count assumes L=64");

// scratch (allocation-free rule: __device__ globals)
__device__ float    g_c   [BSZ * NCHUNK * DM];
__device__ unsigned g_flag[BSZ * NCHUNK];

__global__ void ssm_reset_flags()
{
    g_flag[threadIdx.x] = 0u;
}

__global__ __launch_bounds__(256)
void ssm_fused(const float* __restrict__ x,
               const float* __restrict__ A,
               const float* __restrict__ Bv,
               const float* __restrict__ C,
               const float* __restrict__ Dv,
               const float* __restrict__ gamma,
               const float* __restrict__ beta,
               float* __restrict__ out)
{
    __shared__ float red[2][20];   // [parity][16 warp-partials + 2 broadcast]

    const int b    = blockIdx.y;
    const int ch   = blockIdx.x;
    const int tid  = threadIdx.x;
    const int w    = tid >> 5;
    const int lane = tid & 31;

    const float4 a  = reinterpret_cast<const float4*>(A)[tid];
    const float4 bb = reinterpret_cast<const float4*>(Bv)[tid];

    const size_t base = (size_t)(b * SEQT + ch * CLEN) * ND4 + tid;
    const float4* x4 = reinterpret_cast<const float4*>(x) + base;

    // ---- Phase 1: local scan from zero state -> chunk aggregate c ----
    float4 h = make_float4(0.f, 0.f, 0.f, 0.f);
    #pragma unroll 8
    for (int t = 0; t < CLEN; t++) {
        float4 xv = x4[t * ND4];
        h.x = fmaf(a.x, h.x, bb.x * xv.x);
        h.y = fmaf(a.y, h.y, bb.y * xv.y);
        h.z = fmaf(a.z, h.z, bb.z * xv.z);
        h.w = fmaf(a.w, h.w, bb.w * xv.w);
    }

    const int fid = b * NCHUNK + ch;
    reinterpret_cast<float4*>(g_c)[(size_t)fid * ND4 + tid] = h;
    __threadfence();                          // release: c visible before flag
    __syncthreads();                          // all stores of this block done
    if (tid == 0) atomicExch(&g_flag[fid], 1u);

    // ---- Phase 2: lookback — fold predecessors into chunk-entry state ----
    // aL = A^CLEN = A^64 via 6 squarings
    float4 aL = a;
    #pragma unroll
    for (int i = 0; i < 6; i++) {
        aL.x *= aL.x; aL.y *= aL.y; aL.z *= aL.z; aL.w *= aL.w;
    }

    // parallel poll of all predecessor flags (backward deps only)
    {
        volatile unsigned* vf = (volatile unsigned*)g_flag;
        for (int j = tid; j < ch; j += 256) {
            while (vf[b * NCHUNK + j] == 0u) { }
        }
    }
    __threadfence();                          // acquire: order flag -> c reads
    __syncthreads();

    float4 hin = make_float4(0.f, 0.f, 0.f, 0.f);
    {
        const float4* c4 = reinterpret_cast<const float4*>(g_c)
                           + (size_t)b * NCHUNK * ND4 + tid;
        for (int j = 0; j < ch; j++) {
            float4 cv = c4[j * ND4];
            hin.x = fmaf(aL.x, hin.x, cv.x);
            hin.y = fmaf(aL.y, hin.y, cv.y);
            hin.z = fmaf(aL.z, hin.z, cv.z);
            hin.w = fmaf(aL.w, hin.w, cv.w);
        }
    }

    // ---- Phase 3: re-scan from h_in, fused LayerNorm, write out ----
    const float4 cc = reinterpret_cast<const float4*>(C)[tid];
    const float4 dd = reinterpret_cast<const float4*>(Dv)[tid];
    const float4 gg = reinterpret_cast<const float4*>(gamma)[tid];
    const float4 be = reinterpret_cast<const float4*>(beta)[tid];

    float4* o4 = reinterpret_cast<float4*>(out) + base;

    h = hin;
    float4 xv = x4[0];

    for (int t = 0; t < CLEN; t++) {
        // prefetch next row before the barrier section
        float4 xn;
        if (t + 1 < CLEN) xn = x4[(t + 1) * ND4];

        h.x = fmaf(a.x, h.x, bb.x * xv.x);
        h.y = fmaf(a.y, h.y, bb.y * xv.y);
        h.z = fmaf(a.z, h.z, bb.z * xv.z);
        h.w = fmaf(a.w, h.w, bb.w * xv.w);

        float4 y;
        y.x = fmaf(cc.x, h.x, dd.x * xv.x);
        y.y = fmaf(cc.y, h.y, dd.y * xv.y);
        y.z = fmaf(cc.z, h.z, dd.z * xv.z);
        y.w = fmaf(cc.w, h.w, dd.w * xv.w);

        // block reduction of (sum, sumsq) over the DM row
        float s = y.x + y.y + y.z + y.w;
        float q = fmaf(y.x, y.x, fmaf(y.y, y.y, fmaf(y.z, y.z, y.w * y.w)));
        #pragma unroll
        for (int o = 16; o > 0; o >>= 1) {
            s += __shfl_xor_sync(0xffffffffu, s, o);
            q += __shfl_xor_sync(0xffffffffu, q, o);
        }
        float* rb = red[t & 1];
        if (lane == 0) { rb[2 * w] = s; rb[2 * w + 1] = q; }
        __syncthreads();
        if (w == 0) {
            float ss = (lane < 8) ? rb[2 * lane]     : 0.f;
            float qq = (lane < 8) ? rb[2 * lane + 1] : 0.f;
            #pragma unroll
            for (int o = 4; o > 0; o >>= 1) {
                ss += __shfl_xor_sync(0xffffffffu, ss, o);
                qq += __shfl_xor_sync(0xffffffffu, qq, o);
            }
            if (lane == 0) { rb[16] = ss; rb[17] = qq; }
        }
        __syncthreads();

        const float mu  = rb[16] * (1.f / DM);
        const float var = rb[17] * (1.f / DM) - mu * mu;
        const float inv = rsqrtf(var + LN_EPS);

        float4 o;
        o.x = fmaf((y.x - mu) * inv, gg.x, be.x);
        o.y = fmaf((y.y - mu) * inv, gg.y, be.y);
        o.z = fmaf((y.z - mu) * inv, gg.z, be.z);
        o.w = fmaf((y.w - mu) * inv, gg.w, be.w);
        __stcs(&o4[t * ND4], o);              // streaming store: don't pollute L2

        xv = xn;
    }
}

// ---------------------------------------------------------------------------
extern "C" void kernel_launch(void* const* d_in, const int* in_sizes, int n_in,
                              void* d_out, int out_size)
{
    const float* x     = (const float*)d_in[0];
    const float* A     = (const float*)d_in[1];
    const float* Bv    = (const float*)d_in[2];
    const float* C     = (const float*)d_in[3];
    const float* Dv    = (const float*)d_in[4];
    const float* gamma = (const float*)d_in[5];
    const float* beta  = (const float*)d_in[6];
    float* out = (float*)d_out;

    ssm_reset_flags<<<1, BSZ * NCHUNK>>>();
    dim3 grid(NCHUNK, BSZ);
    ssm_fused<<<grid, 256>>>(x, A, Bv, C, Dv, gamma, beta, out);
}